// round 1
// baseline (speedup 1.0000x reference)
#include <cuda_runtime.h>
#include <math.h>

#define NQ 8
#define DIM 256
#define BATCH 8192
#define INPUT_DIM 3072
#define NCLS 10
#define NGATES 91

// ---------------------------------------------------------------------------
// Device scratch (no allocations allowed)
// ---------------------------------------------------------------------------
struct Gate { int kind1q; int ba; int bb; int pad; float2 m[16]; };

__device__ Gate  g_gates[NGATES];
__device__ float g_Ur[DIM * DIM];       // U stored as [col][k]
__device__ float g_Ui[DIM * DIM];
__device__ float g_A[DIM * DIM];        // Re(U^H Z0 U), row-major [i][j]
__device__ float g_T1[81 * 256];        // partial Pauli transform (qubits 0-3)
__device__ float g_C[6561];             // final 3^8 coefficient tensor
__device__ float g_feats[BATCH * NQ];   // tanh(x@w^T + b)

// ---------------------------------------------------------------------------
// Kernel 1: build the static gate list (schedule is weight-independent;
// matrices come from conv/pool/last params). 1 block, thread 0 builds the
// integer schedule, then 91 threads build matrices in parallel.
// ---------------------------------------------------------------------------
__global__ void prep_gates(const float* __restrict__ conv,
                           const float* __restrict__ pool,
                           const float* __restrict__ last)
{
    __shared__ int sk[NGATES], sa[NGATES], sb[NGATES], sp[NGATES];
    if (threadIdx.x == 0) {
        int ws[8]; for (int i = 0; i < 8; i++) ws[i] = i;
        int nw = 8, gi = 0;
        for (int layer = 0; layer < 2; layer++) {
            int cb = layer * 8 * 15;
            for (int p = 0; p < 2; p++)
                for (int idx = 0; idx < nw - 1; idx++)
                    if ((idx & 1) == p) {
                        int a = ws[idx], b = ws[idx + 1];
                        sk[gi]=0; sa[gi]=a; sb[gi]=0; sp[gi]=cb+idx*15+0;      gi++;
                        sk[gi]=0; sa[gi]=b; sb[gi]=0; sp[gi]=cb+(idx+1)*15+3;  gi++;
                        sk[gi]=1; sa[gi]=a; sb[gi]=b; sp[gi]=cb+idx*15+6;      gi++; // ZZ
                        sk[gi]=2; sa[gi]=a; sb[gi]=b; sp[gi]=cb+idx*15+7;      gi++; // YY
                        sk[gi]=3; sa[gi]=a; sb[gi]=b; sp[gi]=cb+idx*15+8;      gi++; // XX
                        sk[gi]=0; sa[gi]=a; sb[gi]=0; sp[gi]=cb+idx*15+9;      gi++;
                        sk[gi]=0; sa[gi]=b; sb[gi]=0; sp[gi]=cb+(idx+1)*15+12; gi++;
                    }
            int pb = layer * 4 * 3;
            for (int idx = 1; idx < nw; idx += 2) {
                sk[gi]=4; sa[gi]=ws[idx]; sb[gi]=ws[idx-1]; sp[gi]=pb+(idx/2)*3; gi++;
            }
            for (int i = 0; i < nw / 2; i++) ws[i] = ws[2 * i];
            nw /= 2;
        }
        for (int k = 0; k < 15; k++) { sk[gi]=5; sa[gi]=0; sb[gi]=4; sp[gi]=k; gi++; }
    }
    __syncthreads();
    int g = threadIdx.x;
    if (g >= NGATES) return;
    int kind = sk[g], a = sa[g], b = sb[g], o = sp[g];
    Gate gg;
    gg.kind1q = (kind == 0) ? 1 : 0;
    gg.ba = 7 - a; gg.bb = 7 - b; gg.pad = 0;
    for (int i = 0; i < 16; i++) gg.m[i] = make_float2(0.f, 0.f);

    if (kind == 0) {                                  // U3 on wire a
        float t = conv[o], ph = conv[o+1], dl = conv[o+2];
        float ct = cosf(0.5f*t), st = sinf(0.5f*t);
        gg.m[0] = make_float2(ct, 0.f);
        gg.m[1] = make_float2(-cosf(dl)*st, -sinf(dl)*st);
        gg.m[2] = make_float2( cosf(ph)*st,  sinf(ph)*st);
        gg.m[3] = make_float2( cosf(ph+dl)*ct, sinf(ph+dl)*ct);
    } else if (kind <= 3) {                           // Ising exp(-i phi/2 PP)
        float phi = conv[o];
        float c = cosf(0.5f*phi), s = sinf(0.5f*phi);
        if (kind == 1) {                              // ZZ
            gg.m[0]  = make_float2(c, -s); gg.m[5]  = make_float2(c,  s);
            gg.m[10] = make_float2(c,  s); gg.m[15] = make_float2(c, -s);
        } else if (kind == 2) {                       // YY
            gg.m[0]=gg.m[5]=gg.m[10]=gg.m[15]=make_float2(c, 0.f);
            gg.m[3]  = make_float2(0.f,  s); gg.m[6]  = make_float2(0.f, -s);
            gg.m[9]  = make_float2(0.f, -s); gg.m[12] = make_float2(0.f,  s);
        } else {                                      // XX
            gg.m[0]=gg.m[5]=gg.m[10]=gg.m[15]=make_float2(c, 0.f);
            gg.m[3]=gg.m[6]=gg.m[9]=gg.m[12]=make_float2(0.f, -s);
        }
    } else if (kind == 4) {                           // controlled-U3 (ctrl = wire a)
        float t = pool[o], ph = pool[o+1], dl = pool[o+2];
        float ct = cosf(0.5f*t), st = sinf(0.5f*t);
        gg.m[0]  = make_float2(1.f, 0.f);
        gg.m[5]  = make_float2(1.f, 0.f);
        gg.m[10] = make_float2(ct, 0.f);
        gg.m[11] = make_float2(-cosf(dl)*st, -sinf(dl)*st);
        gg.m[14] = make_float2( cosf(ph)*st,  sinf(ph)*st);
        gg.m[15] = make_float2( cosf(ph+dl)*ct, sinf(ph+dl)*ct);
    } else {                                          // Pauli-word rotation on (0,4)
        float th = last[o];
        float c = cosf(0.5f*th), s = sinf(0.5f*th);
        int wa = (o + 1) >> 2, wb = (o + 1) & 3;
        const float2 P[4][4] = {
            { {1,0},{0,0},{0,0},{1,0} },              // I
            { {0,0},{1,0},{1,0},{0,0} },              // X
            { {0,0},{0,-1},{0,1},{0,0} },             // Y
            { {1,0},{0,0},{0,0},{-1,0} }              // Z
        };
        for (int gi2 = 0; gi2 < 4; gi2++)
            for (int h = 0; h < 4; h++) {
                int ga = gi2 >> 1, gbb = gi2 & 1, ha = h >> 1, hb = h & 1;
                float2 wA = P[wa][ga*2+ha], wB = P[wb][gbb*2+hb];
                float2 W = make_float2(wA.x*wB.x - wA.y*wB.y, wA.x*wB.y + wA.y*wB.x);
                float re = (gi2 == h ? c : 0.f) + s * W.y;
                float im = -s * W.x;
                gg.m[gi2*4+h] = make_float2(re, im);
            }
    }
    g_gates[g] = gg;
}

// ---------------------------------------------------------------------------
// Kernel 2: simulate the fixed unitary: block = one basis-state column.
// ---------------------------------------------------------------------------
__global__ void simulate_kernel()
{
    __shared__ float2 amp[256];
    __shared__ float2 gm[16];
    __shared__ int ginfo[3];
    int tid = threadIdx.x;            // 64 threads
    int col = blockIdx.x;
    for (int i = tid; i < 256; i += 64) amp[i] = make_float2(i == col ? 1.f : 0.f, 0.f);
    __syncthreads();
    for (int gidx = 0; gidx < NGATES; gidx++) {
        if (tid < 16) gm[tid] = g_gates[gidx].m[tid];
        if (tid == 16) { ginfo[0] = g_gates[gidx].kind1q;
                         ginfo[1] = g_gates[gidx].ba;
                         ginfo[2] = g_gates[gidx].bb; }
        __syncthreads();
        if (ginfo[0]) {
            int ba = ginfo[1];
            int msk = (1 << ba) - 1;
            #pragma unroll
            for (int r = 0; r < 2; r++) {
                int p = tid + r * 64;
                int i0 = ((p >> ba) << (ba + 1)) | (p & msk);
                int i1 = i0 | (1 << ba);
                float2 v0 = amp[i0], v1 = amp[i1];
                float2 n0, n1;
                n0.x = gm[0].x*v0.x - gm[0].y*v0.y + gm[1].x*v1.x - gm[1].y*v1.y;
                n0.y = gm[0].x*v0.y + gm[0].y*v0.x + gm[1].x*v1.y + gm[1].y*v1.x;
                n1.x = gm[2].x*v0.x - gm[2].y*v0.y + gm[3].x*v1.x - gm[3].y*v1.y;
                n1.y = gm[2].x*v0.y + gm[2].y*v0.x + gm[3].x*v1.y + gm[3].y*v1.x;
                amp[i0] = n0; amp[i1] = n1;
            }
        } else {
            int ba = ginfo[1], bb = ginfo[2];
            int bl = min(ba, bb), bh = max(ba, bb);
            int p = tid;
            int q = ((p >> bl) << (bl + 1)) | (p & ((1 << bl) - 1));
            int base = ((q >> bh) << (bh + 1)) | (q & ((1 << bh) - 1));
            int id0 = base, id1 = base | (1 << bb), id2 = base | (1 << ba), id3 = base | (1 << ba) | (1 << bb);
            float2 v0 = amp[id0], v1 = amp[id1], v2 = amp[id2], v3 = amp[id3];
            float2 nv[4];
            float2 vv[4] = { v0, v1, v2, v3 };
            #pragma unroll
            for (int gg = 0; gg < 4; gg++) {
                float2 acc = make_float2(0.f, 0.f);
                #pragma unroll
                for (int h = 0; h < 4; h++) {
                    float2 mm = gm[gg*4+h];
                    acc.x += mm.x*vv[h].x - mm.y*vv[h].y;
                    acc.y += mm.x*vv[h].y + mm.y*vv[h].x;
                }
                nv[gg] = acc;
            }
            amp[id0] = nv[0]; amp[id1] = nv[1]; amp[id2] = nv[2]; amp[id3] = nv[3];
        }
        __syncthreads();
    }
    for (int k = tid; k < 256; k += 64) {
        g_Ur[col * 256 + k] = amp[k].x;
        g_Ui[col * 256 + k] = amp[k].y;
    }
}

// ---------------------------------------------------------------------------
// Kernel 3: A[i][j] = sum_k sgn(k) * Re(conj(U[k][i]) U[k][j]).
// U stored as [col][k] so tile loads are coalesced over k.
// ---------------------------------------------------------------------------
__global__ void build_A()
{
    __shared__ float ar[32][33], ai[32][33], br[32][33], bi[32][33];
    int tx = threadIdx.x, ty = threadIdx.y;
    int j0 = blockIdx.x * 32, i0 = blockIdx.y * 32;
    float acc = 0.f;
    for (int kc = 0; kc < 256; kc += 32) {
        int k = kc + tx;
        float sg = (k & 128) ? -1.f : 1.f;       // wire 0 <-> bit 7
        ar[ty][tx] = g_Ur[(i0 + ty) * 256 + k] * sg;
        ai[ty][tx] = g_Ui[(i0 + ty) * 256 + k] * sg;
        br[ty][tx] = g_Ur[(j0 + ty) * 256 + k];
        bi[ty][tx] = g_Ui[(j0 + ty) * 256 + k];
        __syncthreads();
        #pragma unroll
        for (int kk = 0; kk < 32; kk++)
            acc += ar[ty][kk] * br[tx][kk] + ai[ty][kk] * bi[tx][kk];
        __syncthreads();
    }
    g_A[(i0 + ty) * 256 + (j0 + tx)] = acc;
}

// ---------------------------------------------------------------------------
// Kernels 4+5: transform A (4^8 pair-index tensor) into the 3^8 coefficient
// tensor over the per-qubit basis {I, X, Z} (sigma_t has 2 nonzeros each).
// ---------------------------------------------------------------------------
__global__ void stage1()   // qubits 0-3 (high nibbles)
{
    int o = blockIdx.x * 256 + threadIdx.x;       // 81*256 = 20736 exact
    int t = o >> 8;
    int ilo = (o >> 4) & 15, jlo = o & 15;
    int d0 = t / 27, r = t % 27;
    int d1 = r / 9; r %= 9;
    int d2 = r / 3, d3 = r % 3;
    int dg[4] = { d0, d1, d2, d3 };
    float sum = 0.f;
    #pragma unroll
    for (int c = 0; c < 16; c++) {
        int ihi = 0, jhi = 0; float sg = 1.f;
        #pragma unroll
        for (int w = 0; w < 4; w++) {
            int b = (c >> w) & 1;
            int d = dg[w];
            int iw = b;
            int jw = (d == 1) ? (1 - b) : b;
            if (d == 2 && b) sg = -sg;
            ihi |= iw << (3 - w);
            jhi |= jw << (3 - w);
        }
        sum += sg * g_A[(ihi * 16 + ilo) * 256 + (jhi * 16 + jlo)];
    }
    g_T1[o] = sum;
}

__global__ void stage2()   // qubits 4-7 (low nibbles)
{
    int o = blockIdx.x * 256 + threadIdx.x;
    if (o >= 6561) return;
    int thi = o / 81, tlo = o % 81;
    int d0 = tlo / 27, r = tlo % 27;
    int d1 = r / 9; r %= 9;
    int d2 = r / 3, d3 = r % 3;
    int dg[4] = { d0, d1, d2, d3 };
    float sum = 0.f;
    #pragma unroll
    for (int c = 0; c < 16; c++) {
        int ilo = 0, jlo = 0; float sg = 1.f;
        #pragma unroll
        for (int w = 0; w < 4; w++) {
            int b = (c >> w) & 1;
            int d = dg[w];
            int iw = b;
            int jw = (d == 1) ? (1 - b) : b;
            if (d == 2 && b) sg = -sg;
            ilo |= iw << (3 - w);
            jlo |= jw << (3 - w);
        }
        sum += sg * g_T1[thi * 256 + ilo * 16 + jlo];
    }
    g_C[o] = sum * (1.f / 256.f);     // (1/2)^8 from M_w = (I + sinX + cosZ)/2
}

// ---------------------------------------------------------------------------
// Kernel 6: feats = tanh(x @ fc_w^T + fc_b). DRAM-bound over x (100 MB).
// 256 blocks x 256 threads; 32 rows/block; w-tile [q][128] in shared
// (conflict-free LDS.128); each lane holds the 8 w-float4s and reuses them
// across 4 rows -> LDS:LDG = 2:1.
// ---------------------------------------------------------------------------
__global__ void __launch_bounds__(256) gemm_feats(const float* __restrict__ x,
                                                  const float* __restrict__ fcw,
                                                  const float* __restrict__ fcb)
{
    __shared__ float wsh[8][128];
    int tid = threadIdx.x;
    int warp = tid >> 5, lane = tid & 31;
    int rowbase = blockIdx.x * 32 + warp * 4;
    const float4* xrow0 = (const float4*)(x + (size_t)(rowbase + 0) * INPUT_DIM);
    const float4* xrow1 = (const float4*)(x + (size_t)(rowbase + 1) * INPUT_DIM);
    const float4* xrow2 = (const float4*)(x + (size_t)(rowbase + 2) * INPUT_DIM);
    const float4* xrow3 = (const float4*)(x + (size_t)(rowbase + 3) * INPUT_DIM);

    float acc[4][8];
    #pragma unroll
    for (int r = 0; r < 4; r++)
        #pragma unroll
        for (int q = 0; q < 8; q++) acc[r][q] = 0.f;

    for (int k0 = 0; k0 < INPUT_DIM; k0 += 128) {
        __syncthreads();
        #pragma unroll
        for (int i = tid; i < 1024; i += 256) {
            int q = i >> 7, kk = i & 127;
            wsh[q][kk] = fcw[q * INPUT_DIM + k0 + kk];
        }
        __syncthreads();
        float4 wv[8];
        #pragma unroll
        for (int q = 0; q < 8; q++) wv[q] = *(const float4*)&wsh[q][lane * 4];
        int kidx = (k0 >> 2) + lane;
        #pragma unroll
        for (int r = 0; r < 4; r++) {
            float4 xv = (r == 0) ? xrow0[kidx] : (r == 1) ? xrow1[kidx]
                       : (r == 2) ? xrow2[kidx] : xrow3[kidx];
            #pragma unroll
            for (int q = 0; q < 8; q++) {
                acc[r][q] = fmaf(xv.x, wv[q].x, acc[r][q]);
                acc[r][q] = fmaf(xv.y, wv[q].y, acc[r][q]);
                acc[r][q] = fmaf(xv.z, wv[q].z, acc[r][q]);
                acc[r][q] = fmaf(xv.w, wv[q].w, acc[r][q]);
            }
        }
    }
    // full butterfly: every lane ends with the complete 32 sums
    #pragma unroll
    for (int r = 0; r < 4; r++)
        #pragma unroll
        for (int q = 0; q < 8; q++) {
            float v = acc[r][q];
            #pragma unroll
            for (int off = 16; off > 0; off >>= 1)
                v += __shfl_xor_sync(0xffffffffu, v, off);
            acc[r][q] = v;
        }
    int rr = lane >> 3, q = lane & 7;
    float val = 0.f;
    #pragma unroll
    for (int r = 0; r < 4; r++)
        #pragma unroll
        for (int qq = 0; qq < 8; qq++)
            if (r == rr && qq == q) val = acc[r][qq];
    g_feats[(rowbase + rr) * 8 + q] = tanhf(val + fcb[q]);
}

// ---------------------------------------------------------------------------
// Kernel 7: per-sample qval = <C, ⊗(1, sin f_w, cos f_w)> and logits.
// C (243 rows x 27, padded to 28) cached in shared; 8 lanes per sample split
// the 243 outer rows; inner 27-dot via LDS.128; shuffle reduce.
// ---------------------------------------------------------------------------
__device__ __forceinline__ float pick3(int d, float sn, float cs)
{
    return (d == 0) ? 1.f : ((d == 1) ? sn : cs);
}

__global__ void __launch_bounds__(256) eval_kernel(const float* __restrict__ outw,
                                                   const float* __restrict__ outb,
                                                   float* __restrict__ logits)
{
    __shared__ float Csh[243 * 28];
    int tid = threadIdx.x;
    for (int i = tid; i < 243 * 28; i += 256) {
        int row = i / 28, c = i % 28;
        Csh[i] = (c < 27) ? g_C[row * 27 + c] : 0.f;
    }
    __syncthreads();

    int part = tid & 7;
    int s = blockIdx.x * 32 + (tid >> 3);
    const float* f = g_feats + s * 8;

    float sn[8], cs[8];
    #pragma unroll
    for (int w = 0; w < 8; w++) __sincosf(f[w], &sn[w], &cs[w]);

    float4 g4[7];
    {
        float* g = (float*)g4;
        #pragma unroll
        for (int a = 0; a < 3; a++) {
            float ua = pick3(a, sn[5], cs[5]);
            #pragma unroll
            for (int b = 0; b < 3; b++) {
                float uab = ua * pick3(b, sn[6], cs[6]);
                #pragma unroll
                for (int c = 0; c < 3; c++)
                    g[a * 9 + b * 3 + c] = uab * pick3(c, sn[7], cs[7]);
            }
        }
        g[27] = 0.f;
    }

    int start = part * 31;
    int end = min(243, start + 31);
    int d0 = start / 81, r0 = start % 81;
    int d1 = r0 / 27; r0 %= 27;
    int d2 = r0 / 9;  r0 %= 9;
    int d3 = r0 / 3,  d4 = r0 % 3;

    float acc = 0.f;
    for (int o = start; o < end; o++) {
        float p = pick3(d0, sn[0], cs[0]) * pick3(d1, sn[1], cs[1]);
        p *= pick3(d2, sn[2], cs[2]);
        p *= pick3(d3, sn[3], cs[3]);
        p *= pick3(d4, sn[4], cs[4]);
        const float4* crow = (const float4*)&Csh[o * 28];
        float dsum = 0.f;
        #pragma unroll
        for (int j = 0; j < 7; j++) {
            float4 cv = crow[j], gv = g4[j];
            dsum = fmaf(cv.x, gv.x, dsum);
            dsum = fmaf(cv.y, gv.y, dsum);
            dsum = fmaf(cv.z, gv.z, dsum);
            dsum = fmaf(cv.w, gv.w, dsum);
        }
        acc = fmaf(p, dsum, acc);
        d4++;
        if (d4 == 3) { d4 = 0; d3++;
            if (d3 == 3) { d3 = 0; d2++;
                if (d2 == 3) { d2 = 0; d1++;
                    if (d1 == 3) { d1 = 0; d0++; } } } }
    }
    acc += __shfl_xor_sync(0xffffffffu, acc, 1);
    acc += __shfl_xor_sync(0xffffffffu, acc, 2);
    acc += __shfl_xor_sync(0xffffffffu, acc, 4);

    for (int c = part; c < NCLS; c += 8)
        logits[s * NCLS + c] = fmaf(acc, outw[c], outb[c]);
}

// ---------------------------------------------------------------------------
extern "C" void kernel_launch(void* const* d_in, const int* in_sizes, int n_in,
                              void* d_out, int out_size)
{
    const float* x    = (const float*)d_in[0];
    const float* fcw  = (const float*)d_in[1];
    const float* fcb  = (const float*)d_in[2];
    const float* conv = (const float*)d_in[3];
    const float* pool = (const float*)d_in[4];
    const float* last = (const float*)d_in[5];
    const float* outw = (const float*)d_in[6];
    const float* outb = (const float*)d_in[7];
    float* out = (float*)d_out;

    prep_gates<<<1, 128>>>(conv, pool, last);
    simulate_kernel<<<256, 64>>>();
    build_A<<<dim3(8, 8), dim3(32, 32)>>>();
    stage1<<<81, 256>>>();
    stage2<<<26, 256>>>();
    gemm_feats<<<256, 256>>>(x, fcw, fcb);
    eval_kernel<<<256, 256>>>(outw, outb, out);
}

// round 3
// speedup vs baseline: 1.9240x; 1.9240x over previous
#include <cuda_runtime.h>
#include <math.h>

#define NQ 8
#define DIM 256
#define BATCH 8192
#define INPUT_DIM 3072
#define NCLS 10
#define NMERGED 17

// ---------------------------------------------------------------------------
// Device scratch
// ---------------------------------------------------------------------------
__device__ float g_Ur[DIM * DIM];       // U stored as [col][k]
__device__ float g_Ui[DIM * DIM];
__device__ float g_A[DIM * DIM];        // Re(U^H Z0 U), row-major [i][j]
__device__ float g_T1[81 * 256];        // partial Pauli transform (qubits 0-3)
__device__ float g_C[6561];             // final 3^8 coefficient tensor
__device__ float g_feats[BATCH * NQ];   // tanh(x@w^T + b)

// ---------------------------------------------------------------------------
// complex helpers
// ---------------------------------------------------------------------------
__device__ __forceinline__ float2 cmul(float2 a, float2 b) {
    return make_float2(a.x*b.x - a.y*b.y, a.x*b.y + a.y*b.x);
}
__device__ __forceinline__ float2 cfma(float2 a, float2 b, float2 c) {
    return make_float2(fmaf(a.x,b.x,fmaf(-a.y,b.y,c.x)),
                       fmaf(a.x,b.y,fmaf( a.y,b.x,c.y)));
}
__device__ __forceinline__ void u3fill(float t, float p, float d, float2 u[4]) {
    float ct = cosf(0.5f*t), st = sinf(0.5f*t);
    u[0] = make_float2(ct, 0.f);
    u[1] = make_float2(-cosf(d)*st, -sinf(d)*st);
    u[2] = make_float2( cosf(p)*st,  sinf(p)*st);
    u[3] = make_float2( cosf(p+d)*ct, sinf(p+d)*ct);
}

// ---------------------------------------------------------------------------
// Kernel 1: fused prep + simulate.
// Build order (index into mged):
//   0-6  : conv blocks layer0  pairs (0,1),(2,3),(4,5),(6,7),(1,2),(3,4),(5,6)
//   7-9  : conv blocks layer1  pairs (0,2),(4,6),(2,4)
//   10-13: pool layer0         (ctrl,tgt) = (1,0),(3,2),(5,4),(7,6)
//   14-15: pool layer1         (2,0),(6,4)
//   16   : merged last-layer Pauli rotations on (0,4)
// Application (circuit) order = appOrder[] permutation of the above.
// ---------------------------------------------------------------------------
__global__ void __launch_bounds__(256) sim_all(const float* __restrict__ conv,
                                               const float* __restrict__ pool,
                                               const float* __restrict__ last)
{
    __shared__ float2 elemBuf[71][16];      // 50 conv + 6 pool + 15 last
    __shared__ float2 mgbuf[2][16][16];     // ping-pong for merged gates 0..15
    __shared__ float2 lastbuf[2][16];       // ping-pong for gate 16 chain
    __shared__ float2 mged[NMERGED][16];    // final merged gates (build order)
    __shared__ float2 amp[8][256];          // 8 columns per block

    const int t = threadIdx.x;
    const int g = t >> 4, l = t & 15;

    // conv gate tables (build gates 0..9): layer and wires-array position idx
    const int convL[10] = {0,0,0,0,0,0,0,1,1,1};
    const int convI[10] = {0,2,4,6,1,3,5,0,2,1};
    // pool tables (build gates 10..15)
    const int poolL[6]  = {0,0,0,0,1,1};
    const int poolR[6]  = {0,1,2,3,0,1};

    // ---------------- build elementary 4x4 gates -------------------------
    if (g < 10 && l < 5) {                          // conv elementary
        int L = convL[g], I = convI[g];
        const float* cw = conv + L * 120;
        float2 m[16];
        #pragma unroll
        for (int i = 0; i < 16; i++) m[i] = make_float2(0.f, 0.f);
        if (l == 0 || l == 4) {
            float2 ua[4], ub[4];
            if (l == 0) {
                u3fill(cw[I*15+0],  cw[I*15+1],  cw[I*15+2],  ua);
                u3fill(cw[(I+1)*15+3], cw[(I+1)*15+4], cw[(I+1)*15+5], ub);
            } else {
                u3fill(cw[I*15+9],  cw[I*15+10], cw[I*15+11], ua);
                u3fill(cw[(I+1)*15+12], cw[(I+1)*15+13], cw[(I+1)*15+14], ub);
            }
            for (int ga = 0; ga < 2; ga++)
                for (int gb = 0; gb < 2; gb++)
                    for (int ha = 0; ha < 2; ha++)
                        for (int hb = 0; hb < 2; hb++)
                            m[(ga*2+gb)*4 + (ha*2+hb)] = cmul(ua[ga*2+ha], ub[gb*2+hb]);
        } else {
            float phi = cw[I*15 + 5 + l];           // l=1:ZZ(6) l=2:YY(7) l=3:XX(8)
            float c = cosf(0.5f*phi), s = sinf(0.5f*phi);
            if (l == 1) {                           // ZZ
                m[0]  = make_float2(c,-s); m[5]  = make_float2(c, s);
                m[10] = make_float2(c, s); m[15] = make_float2(c,-s);
            } else if (l == 2) {                    // YY
                m[0]=m[5]=m[10]=m[15]=make_float2(c,0.f);
                m[3]  = make_float2(0.f, s); m[6]  = make_float2(0.f,-s);
                m[9]  = make_float2(0.f,-s); m[12] = make_float2(0.f, s);
            } else {                                // XX
                m[0]=m[5]=m[10]=m[15]=make_float2(c,0.f);
                m[3]=m[6]=m[9]=m[12]=make_float2(0.f,-s);
            }
        }
        #pragma unroll
        for (int i = 0; i < 16; i++) elemBuf[g*5+l][i] = m[i];
    }
    if (g >= 10 && g < 16 && l == 0) {              // pool CU3 (ctrl = first idx)
        int pg = g - 10;
        int po = poolL[pg]*12 + poolR[pg]*3;
        float tt = pool[po], pp = pool[po+1], dd = pool[po+2];
        float ct = cosf(0.5f*tt), st = sinf(0.5f*tt);
        float2 m[16];
        #pragma unroll
        for (int i = 0; i < 16; i++) m[i] = make_float2(0.f, 0.f);
        m[0]  = make_float2(1.f, 0.f);
        m[5]  = make_float2(1.f, 0.f);
        m[10] = make_float2(ct, 0.f);
        m[11] = make_float2(-cosf(dd)*st, -sinf(dd)*st);
        m[14] = make_float2( cosf(pp)*st,  sinf(pp)*st);
        m[15] = make_float2( cosf(pp+dd)*ct, sinf(pp+dd)*ct);
        #pragma unroll
        for (int i = 0; i < 16; i++) elemBuf[50+pg][i] = m[i];
    }
    if (g == 15 && l >= 1) {                        // last-layer Pauli rotations
        int k = l - 1;
        float th = last[k];
        float c = cosf(0.5f*th), s = sinf(0.5f*th);
        int wa = (k + 1) >> 2, wb = (k + 1) & 3;
        const float2 P[4][4] = {
            { {1,0},{0,0},{0,0},{1,0} },
            { {0,0},{1,0},{1,0},{0,0} },
            { {0,0},{0,-1},{0,1},{0,0} },
            { {1,0},{0,0},{0,0},{-1,0} }
        };
        float2 m[16];
        for (int gi = 0; gi < 4; gi++)
            for (int h = 0; h < 4; h++) {
                int ga = gi >> 1, gb = gi & 1, ha = h >> 1, hb = h & 1;
                float2 wA = P[wa][ga*2+ha], wB = P[wb][gb*2+hb];
                float2 W = cmul(wA, wB);
                m[gi*4+h] = make_float2((gi == h ? c : 0.f) + s * W.y, -s * W.x);
            }
        #pragma unroll
        for (int i = 0; i < 16; i++) elemBuf[56+k][i] = m[i];
    }
    __syncthreads();

    // ---------------- phase A: merge gates 0..15 (max chain 5) ------------
    {
        int len = (g < 10) ? 5 : 1;
        int eb  = (g < 10) ? g*5 : 50 + (g - 10);
        int r = l >> 2, c = l & 3;
        int cur = 0;
        mgbuf[0][g][l] = elemBuf[eb][l];
        for (int i = 1; i < 5; i++) {
            __syncthreads();
            float2 v;
            if (i < len) {
                float2 acc = make_float2(0.f, 0.f);
                #pragma unroll
                for (int k = 0; k < 4; k++)
                    acc = cfma(elemBuf[eb+i][r*4+k], mgbuf[cur][g][k*4+c], acc);
                v = acc;
            } else v = mgbuf[cur][g][l];
            mgbuf[cur^1][g][l] = v;
            cur ^= 1;
        }
        mged[g][l] = mgbuf[cur][g][l];
    }
    // ---------------- phase B: merge gate 16 (15-long chain, warp 0) ------
    if (t < 16) {
        int r = t >> 2, c = t & 3, cur = 0;
        lastbuf[0][t] = elemBuf[56][t];
        __syncwarp(0x0000ffffu);
        for (int i = 1; i < 15; i++) {
            float2 acc = make_float2(0.f, 0.f);
            #pragma unroll
            for (int k = 0; k < 4; k++)
                acc = cfma(elemBuf[56+i][r*4+k], lastbuf[cur][k*4+c], acc);
            lastbuf[cur^1][t] = acc;
            __syncwarp(0x0000ffffu);
            cur ^= 1;
        }
        mged[16][t] = lastbuf[cur][t];
    }
    __syncthreads();

    // ---------------- simulation: one warp per column ---------------------
    // Application (circuit) order; mba/mbb = (7-wireA, 7-wireB) per app slot:
    //  app 0-6  : layer0 conv   (0,1)(2,3)(4,5)(6,7)(1,2)(3,4)(5,6)
    //  app 7-10 : layer0 pool   (1,0)(3,2)(5,4)(7,6)
    //  app 11-13: layer1 conv   (0,2)(4,6)(2,4)
    //  app 14-15: layer1 pool   (2,0)(6,4)
    //  app 16   : last          (0,4)
    const int appOrder[NMERGED] = {0,1,2,3,4,5,6, 10,11,12,13, 7,8,9, 14,15, 16};
    const int mba[NMERGED] = {7,5,3,1,6,4,2, 6,4,2,0, 7,3,5, 5,1, 7};
    const int mbb[NMERGED] = {6,4,2,0,5,3,1, 7,5,3,1, 5,1,3, 7,3, 3};

    const int warp = t >> 5, lane = t & 31;
    const int col = blockIdx.x * 8 + warp;
    for (int i = lane; i < 256; i += 32)
        amp[warp][i] = make_float2(i == col ? 1.f : 0.f, 0.f);
    __syncwarp();

    for (int gg = 0; gg < NMERGED; gg++) {
        int ba = mba[gg], bb = mbb[gg];
        int bl = min(ba, bb), bh = max(ba, bb);
        const int src = appOrder[gg];
        float2 m[16];
        #pragma unroll
        for (int i = 0; i < 16; i++) m[i] = mged[src][i];
        #pragma unroll
        for (int r = 0; r < 2; r++) {
            int p = lane + 32 * r;
            int q = ((p >> bl) << (bl + 1)) | (p & ((1 << bl) - 1));
            int base = ((q >> bh) << (bh + 1)) | (q & ((1 << bh) - 1));
            int i1 = base | (1 << bb);
            int i2 = base | (1 << ba);
            int i3 = i1 | i2;
            float2 vv[4] = { amp[warp][base], amp[warp][i1],
                             amp[warp][i2],   amp[warp][i3] };
            float2 nv[4];
            #pragma unroll
            for (int a = 0; a < 4; a++) {
                float2 acc = make_float2(0.f, 0.f);
                #pragma unroll
                for (int h = 0; h < 4; h++)
                    acc = cfma(m[a*4+h], vv[h], acc);
                nv[a] = acc;
            }
            amp[warp][base] = nv[0]; amp[warp][i1] = nv[1];
            amp[warp][i2]   = nv[2]; amp[warp][i3] = nv[3];
        }
        __syncwarp();
    }

    for (int k = lane; k < 256; k += 32) {
        g_Ur[col * 256 + k] = amp[warp][k].x;
        g_Ui[col * 256 + k] = amp[warp][k].y;
    }
}

// ---------------------------------------------------------------------------
// Kernel 2: A[i][j] = sum_k sgn(k) * Re(conj(U[k][i]) U[k][j]).
// ---------------------------------------------------------------------------
__global__ void build_A()
{
    __shared__ float ar[32][33], ai[32][33], br[32][33], bi[32][33];
    int tx = threadIdx.x, ty = threadIdx.y;
    int j0 = blockIdx.x * 32, i0 = blockIdx.y * 32;
    float acc = 0.f;
    for (int kc = 0; kc < 256; kc += 32) {
        int k = kc + tx;
        float sg = (k & 128) ? -1.f : 1.f;       // wire 0 <-> bit 7
        ar[ty][tx] = g_Ur[(i0 + ty) * 256 + k] * sg;
        ai[ty][tx] = g_Ui[(i0 + ty) * 256 + k] * sg;
        br[ty][tx] = g_Ur[(j0 + ty) * 256 + k];
        bi[ty][tx] = g_Ui[(j0 + ty) * 256 + k];
        __syncthreads();
        #pragma unroll
        for (int kk = 0; kk < 32; kk++)
            acc += ar[ty][kk] * br[tx][kk] + ai[ty][kk] * bi[tx][kk];
        __syncthreads();
    }
    g_A[(i0 + ty) * 256 + (j0 + tx)] = acc;
}

// ---------------------------------------------------------------------------
// Kernels 3+4: transform A into the 3^8 coefficient tensor over {I,X,Z}.
// ---------------------------------------------------------------------------
__global__ void stage1()   // qubits 0-3 (high nibbles)
{
    int o = blockIdx.x * 256 + threadIdx.x;       // 81*256 = 20736 exact
    int t = o >> 8;
    int ilo = (o >> 4) & 15, jlo = o & 15;
    int d0 = t / 27, r = t % 27;
    int d1 = r / 9; r %= 9;
    int d2 = r / 3, d3 = r % 3;
    int dg[4] = { d0, d1, d2, d3 };
    float sum = 0.f;
    #pragma unroll
    for (int c = 0; c < 16; c++) {
        int ihi = 0, jhi = 0; float sg = 1.f;
        #pragma unroll
        for (int w = 0; w < 4; w++) {
            int b = (c >> w) & 1;
            int d = dg[w];
            int iw = b;
            int jw = (d == 1) ? (1 - b) : b;
            if (d == 2 && b) sg = -sg;
            ihi |= iw << (3 - w);
            jhi |= jw << (3 - w);
        }
        sum += sg * g_A[(ihi * 16 + ilo) * 256 + (jhi * 16 + jlo)];
    }
    g_T1[o] = sum;
}

__global__ void stage2()   // qubits 4-7 (low nibbles)
{
    int o = blockIdx.x * 256 + threadIdx.x;
    if (o >= 6561) return;
    int thi = o / 81, tlo = o % 81;
    int d0 = tlo / 27, r = tlo % 27;
    int d1 = r / 9; r %= 9;
    int d2 = r / 3, d3 = r % 3;
    int dg[4] = { d0, d1, d2, d3 };
    float sum = 0.f;
    #pragma unroll
    for (int c = 0; c < 16; c++) {
        int ilo = 0, jlo = 0; float sg = 1.f;
        #pragma unroll
        for (int w = 0; w < 4; w++) {
            int b = (c >> w) & 1;
            int d = dg[w];
            int iw = b;
            int jw = (d == 1) ? (1 - b) : b;
            if (d == 2 && b) sg = -sg;
            ilo |= iw << (3 - w);
            jlo |= jw << (3 - w);
        }
        sum += sg * g_T1[thi * 256 + ilo * 16 + jlo];
    }
    g_C[o] = sum * (1.f / 256.f);
}

// ---------------------------------------------------------------------------
// Kernel 5: feats = tanh(x @ fc_w^T + fc_b). DRAM-bound over x (100 MB).
// 1024 blocks x 128 threads, 8 rows/block, 2 rows/warp; no smem, no syncs;
// w (96 KB) stays L1/L2-resident, entire grid resident in one wave.
// ---------------------------------------------------------------------------
__global__ void __launch_bounds__(128) gemm_feats(const float* __restrict__ x,
                                                  const float* __restrict__ fcw,
                                                  const float* __restrict__ fcb)
{
    int warp = threadIdx.x >> 5, lane = threadIdx.x & 31;
    int row0 = blockIdx.x * 8 + warp * 2;
    const float4* __restrict__ x0 = (const float4*)(x + (size_t)row0 * INPUT_DIM);
    const float4* __restrict__ x1 = x0 + (INPUT_DIM / 4);
    const float4* __restrict__ w4 = (const float4*)fcw;

    float acc0[8], acc1[8];
    #pragma unroll
    for (int q = 0; q < 8; q++) { acc0[q] = 0.f; acc1[q] = 0.f; }

    #pragma unroll 2
    for (int kc = lane; kc < INPUT_DIM / 4; kc += 32) {
        float4 xa = x0[kc];
        float4 xb = x1[kc];
        #pragma unroll
        for (int q = 0; q < 8; q++) {
            float4 wv = w4[q * (INPUT_DIM / 4) + kc];
            acc0[q] = fmaf(xa.x, wv.x, fmaf(xa.y, wv.y, fmaf(xa.z, wv.z, fmaf(xa.w, wv.w, acc0[q]))));
            acc1[q] = fmaf(xb.x, wv.x, fmaf(xb.y, wv.y, fmaf(xb.z, wv.z, fmaf(xb.w, wv.w, acc1[q]))));
        }
    }
    #pragma unroll
    for (int q = 0; q < 8; q++) {
        #pragma unroll
        for (int off = 16; off > 0; off >>= 1) {
            acc0[q] += __shfl_xor_sync(0xffffffffu, acc0[q], off);
            acc1[q] += __shfl_xor_sync(0xffffffffu, acc1[q], off);
        }
    }
    int sel = lane & 7;
    float v0 = 0.f, v1 = 0.f;
    #pragma unroll
    for (int q = 0; q < 8; q++)
        if (q == sel) { v0 = acc0[q]; v1 = acc1[q]; }
    if (lane < 8)
        g_feats[row0 * 8 + sel] = tanhf(v0 + fcb[sel]);
    else if (lane < 16)
        g_feats[(row0 + 1) * 8 + sel] = tanhf(v1 + fcb[sel]);
}

// ---------------------------------------------------------------------------
// Kernel 6: per-sample qval = <C, ⊗(1, sin f_w, cos f_w)> and logits.
// ---------------------------------------------------------------------------
__device__ __forceinline__ float pick3(int d, float sn, float cs)
{
    return (d == 0) ? 1.f : ((d == 1) ? sn : cs);
}

__global__ void __launch_bounds__(256) eval_kernel(const float* __restrict__ outw,
                                                   const float* __restrict__ outb,
                                                   float* __restrict__ logits)
{
    __shared__ float Csh[243 * 28];
    int tid = threadIdx.x;
    for (int i = tid; i < 243 * 28; i += 256) {
        int row = i / 28, c = i % 28;
        Csh[i] = (c < 27) ? g_C[row * 27 + c] : 0.f;
    }
    __syncthreads();

    int part = tid & 7;
    int s = blockIdx.x * 32 + (tid >> 3);
    const float* f = g_feats + s * 8;

    float sn[8], cs[8];
    #pragma unroll
    for (int w = 0; w < 8; w++) __sincosf(f[w], &sn[w], &cs[w]);

    float4 g4[7];
    {
        float* g = (float*)g4;
        #pragma unroll
        for (int a = 0; a < 3; a++) {
            float ua = pick3(a, sn[5], cs[5]);
            #pragma unroll
            for (int b = 0; b < 3; b++) {
                float uab = ua * pick3(b, sn[6], cs[6]);
                #pragma unroll
                for (int c = 0; c < 3; c++)
                    g[a * 9 + b * 3 + c] = uab * pick3(c, sn[7], cs[7]);
            }
        }
        g[27] = 0.f;
    }

    int start = part * 31;
    int end = min(243, start + 31);
    int d0 = start / 81, r0 = start % 81;
    int d1 = r0 / 27; r0 %= 27;
    int d2 = r0 / 9;  r0 %= 9;
    int d3 = r0 / 3,  d4 = r0 % 3;

    float acc = 0.f;
    for (int o = start; o < end; o++) {
        float p = pick3(d0, sn[0], cs[0]) * pick3(d1, sn[1], cs[1]);
        p *= pick3(d2, sn[2], cs[2]);
        p *= pick3(d3, sn[3], cs[3]);
        p *= pick3(d4, sn[4], cs[4]);
        const float4* crow = (const float4*)&Csh[o * 28];
        float dsum = 0.f;
        #pragma unroll
        for (int j = 0; j < 7; j++) {
            float4 cv = crow[j], gv = g4[j];
            dsum = fmaf(cv.x, gv.x, dsum);
            dsum = fmaf(cv.y, gv.y, dsum);
            dsum = fmaf(cv.z, gv.z, dsum);
            dsum = fmaf(cv.w, gv.w, dsum);
        }
        acc = fmaf(p, dsum, acc);
        d4++;
        if (d4 == 3) { d4 = 0; d3++;
            if (d3 == 3) { d3 = 0; d2++;
                if (d2 == 3) { d2 = 0; d1++;
                    if (d1 == 3) { d1 = 0; d0++; } } } }
    }
    acc += __shfl_xor_sync(0xffffffffu, acc, 1);
    acc += __shfl_xor_sync(0xffffffffu, acc, 2);
    acc += __shfl_xor_sync(0xffffffffu, acc, 4);

    for (int c = part; c < NCLS; c += 8)
        logits[s * NCLS + c] = fmaf(acc, outw[c], outb[c]);
}

// ---------------------------------------------------------------------------
extern "C" void kernel_launch(void* const* d_in, const int* in_sizes, int n_in,
                              void* d_out, int out_size)
{
    const float* x    = (const float*)d_in[0];
    const float* fcw  = (const float*)d_in[1];
    const float* fcb  = (const float*)d_in[2];
    const float* conv = (const float*)d_in[3];
    const float* pool = (const float*)d_in[4];
    const float* last = (const float*)d_in[5];
    const float* outw = (const float*)d_in[6];
    const float* outb = (const float*)d_in[7];
    float* out = (float*)d_out;

    sim_all<<<32, 256>>>(conv, pool, last);
    build_A<<<dim3(8, 8), dim3(32, 32)>>>();
    stage1<<<81, 256>>>();
    stage2<<<26, 256>>>();
    gemm_feats<<<1024, 128>>>(x, fcw, fcb);
    eval_kernel<<<256, 256>>>(outw, outb, out);
}

// round 5
// speedup vs baseline: 2.3895x; 1.2419x over previous
#include <cuda_runtime.h>
#include <math.h>

#define NQ 8
#define DIM 256
#define BATCH 8192
#define INPUT_DIM 3072
#define NCLS 10
#define NMERGED 17

// ---------------------------------------------------------------------------
// Device scratch
// ---------------------------------------------------------------------------
__device__ float2 g_U[DIM * DIM];       // U interleaved: g_U[col*256 + k] = U[k][col]
__device__ float  g_A[DIM * DIM];       // Re(U^H Z0 U), row-major [i][j]
__device__ float  g_T1[81 * 256];       // partial Pauli transform (qubits 0-3)
__device__ float  g_C[243 * 28];        // final 3^8 coeff tensor, padded rows
// ---------------------------------------------------------------------------
// complex helpers
// ---------------------------------------------------------------------------
__device__ __forceinline__ float2 cmul(float2 a, float2 b) {
    return make_float2(a.x*b.x - a.y*b.y, a.x*b.y + a.y*b.x);
}
__device__ __forceinline__ float2 cfma(float2 a, float2 b, float2 c) {
    return make_float2(fmaf(a.x,b.x,fmaf(-a.y,b.y,c.x)),
                       fmaf(a.x,b.y,fmaf( a.y,b.x,c.y)));
}
__device__ __forceinline__ void u3fill(float t, float p, float d, float2 u[4]) {
    float ct = cosf(0.5f*t), st = sinf(0.5f*t);
    u[0] = make_float2(ct, 0.f);
    u[1] = make_float2(-cosf(d)*st, -sinf(d)*st);
    u[2] = make_float2( cosf(p)*st,  sinf(p)*st);
    u[3] = make_float2( cosf(p+d)*ct, sinf(p+d)*ct);
}
// packed f32x2 fma
__device__ __forceinline__ unsigned long long ffma2(unsigned long long a,
                                                    unsigned long long b,
                                                    unsigned long long c) {
    unsigned long long d;
    asm("fma.rn.f32x2 %0, %1, %2, %3;" : "=l"(d) : "l"(a), "l"(b), "l"(c));
    return d;
}

// ---------------------------------------------------------------------------
// Kernel 1: fused prep + simulate (math identical to R3-passing version,
// plus: zeroes g_A for split-k atomics, writes U interleaved).
// ---------------------------------------------------------------------------
__global__ void __launch_bounds__(256) sim_all(const float* __restrict__ conv,
                                               const float* __restrict__ pool,
                                               const float* __restrict__ last)
{
    __shared__ float2 elemBuf[71][16];
    __shared__ float2 mgbuf[2][16][16];
    __shared__ float2 lastbuf[2][16];
    __shared__ float2 mged[NMERGED][16];
    __shared__ float2 amp[8][256];

    const int t = threadIdx.x;
    const int g = t >> 4, l = t & 15;

    // zero g_A (needed before build_A's atomicAdd)
    {
        int idx = blockIdx.x * 256 + t;           // 8192 threads, 8 floats each
        float4 z = make_float4(0.f, 0.f, 0.f, 0.f);
        ((float4*)g_A)[idx * 2]     = z;
        ((float4*)g_A)[idx * 2 + 1] = z;
    }

    const int convL[10] = {0,0,0,0,0,0,0,1,1,1};
    const int convI[10] = {0,2,4,6,1,3,5,0,2,1};
    const int poolL[6]  = {0,0,0,0,1,1};
    const int poolR[6]  = {0,1,2,3,0,1};

    if (g < 10 && l < 5) {
        int L = convL[g], I = convI[g];
        const float* cw = conv + L * 120;
        float2 m[16];
        #pragma unroll
        for (int i = 0; i < 16; i++) m[i] = make_float2(0.f, 0.f);
        if (l == 0 || l == 4) {
            float2 ua[4], ub[4];
            if (l == 0) {
                u3fill(cw[I*15+0],  cw[I*15+1],  cw[I*15+2],  ua);
                u3fill(cw[(I+1)*15+3], cw[(I+1)*15+4], cw[(I+1)*15+5], ub);
            } else {
                u3fill(cw[I*15+9],  cw[I*15+10], cw[I*15+11], ua);
                u3fill(cw[(I+1)*15+12], cw[(I+1)*15+13], cw[(I+1)*15+14], ub);
            }
            for (int ga = 0; ga < 2; ga++)
                for (int gb = 0; gb < 2; gb++)
                    for (int ha = 0; ha < 2; ha++)
                        for (int hb = 0; hb < 2; hb++)
                            m[(ga*2+gb)*4 + (ha*2+hb)] = cmul(ua[ga*2+ha], ub[gb*2+hb]);
        } else {
            float phi = cw[I*15 + 5 + l];
            float c = cosf(0.5f*phi), s = sinf(0.5f*phi);
            if (l == 1) {
                m[0]  = make_float2(c,-s); m[5]  = make_float2(c, s);
                m[10] = make_float2(c, s); m[15] = make_float2(c,-s);
            } else if (l == 2) {
                m[0]=m[5]=m[10]=m[15]=make_float2(c,0.f);
                m[3]  = make_float2(0.f, s); m[6]  = make_float2(0.f,-s);
                m[9]  = make_float2(0.f,-s); m[12] = make_float2(0.f, s);
            } else {
                m[0]=m[5]=m[10]=m[15]=make_float2(c,0.f);
                m[3]=m[6]=m[9]=m[12]=make_float2(0.f,-s);
            }
        }
        #pragma unroll
        for (int i = 0; i < 16; i++) elemBuf[g*5+l][i] = m[i];
    }
    if (g >= 10 && g < 16 && l == 0) {
        int pg = g - 10;
        int po = poolL[pg]*12 + poolR[pg]*3;
        float tt = pool[po], pp = pool[po+1], dd = pool[po+2];
        float ct = cosf(0.5f*tt), st = sinf(0.5f*tt);
        float2 m[16];
        #pragma unroll
        for (int i = 0; i < 16; i++) m[i] = make_float2(0.f, 0.f);
        m[0]  = make_float2(1.f, 0.f);
        m[5]  = make_float2(1.f, 0.f);
        m[10] = make_float2(ct, 0.f);
        m[11] = make_float2(-cosf(dd)*st, -sinf(dd)*st);
        m[14] = make_float2( cosf(pp)*st,  sinf(pp)*st);
        m[15] = make_float2( cosf(pp+dd)*ct, sinf(pp+dd)*ct);
        #pragma unroll
        for (int i = 0; i < 16; i++) elemBuf[50+pg][i] = m[i];
    }
    if (g == 15 && l >= 1) {
        int k = l - 1;
        float th = last[k];
        float c = cosf(0.5f*th), s = sinf(0.5f*th);
        int wa = (k + 1) >> 2, wb = (k + 1) & 3;
        const float2 P[4][4] = {
            { {1,0},{0,0},{0,0},{1,0} },
            { {0,0},{1,0},{1,0},{0,0} },
            { {0,0},{0,-1},{0,1},{0,0} },
            { {1,0},{0,0},{0,0},{-1,0} }
        };
        float2 m[16];
        for (int gi = 0; gi < 4; gi++)
            for (int h = 0; h < 4; h++) {
                int ga = gi >> 1, gb = gi & 1, ha = h >> 1, hb = h & 1;
                float2 wA = P[wa][ga*2+ha], wB = P[wb][gb*2+hb];
                float2 W = cmul(wA, wB);
                m[gi*4+h] = make_float2((gi == h ? c : 0.f) + s * W.y, -s * W.x);
            }
        #pragma unroll
        for (int i = 0; i < 16; i++) elemBuf[56+k][i] = m[i];
    }
    __syncthreads();

    {   // merge gates 0..15 (chain length up to 5)
        int len = (g < 10) ? 5 : 1;
        int eb  = (g < 10) ? g*5 : 50 + (g - 10);
        int r = l >> 2, c = l & 3;
        int cur = 0;
        mgbuf[0][g][l] = elemBuf[eb][l];
        for (int i = 1; i < 5; i++) {
            __syncthreads();
            float2 v;
            if (i < len) {
                float2 acc = make_float2(0.f, 0.f);
                #pragma unroll
                for (int k = 0; k < 4; k++)
                    acc = cfma(elemBuf[eb+i][r*4+k], mgbuf[cur][g][k*4+c], acc);
                v = acc;
            } else v = mgbuf[cur][g][l];
            mgbuf[cur^1][g][l] = v;
            cur ^= 1;
        }
        mged[g][l] = mgbuf[cur][g][l];
    }
    if (t < 16) {   // merge gate 16 (15-long chain)
        int r = t >> 2, c = t & 3, cur = 0;
        lastbuf[0][t] = elemBuf[56][t];
        __syncwarp(0x0000ffffu);
        for (int i = 1; i < 15; i++) {
            float2 acc = make_float2(0.f, 0.f);
            #pragma unroll
            for (int k = 0; k < 4; k++)
                acc = cfma(elemBuf[56+i][r*4+k], lastbuf[cur][k*4+c], acc);
            lastbuf[cur^1][t] = acc;
            __syncwarp(0x0000ffffu);
            cur ^= 1;
        }
        mged[16][t] = lastbuf[cur][t];
    }
    __syncthreads();

    const int appOrder[NMERGED] = {0,1,2,3,4,5,6, 10,11,12,13, 7,8,9, 14,15, 16};
    const int mba[NMERGED] = {7,5,3,1,6,4,2, 6,4,2,0, 7,3,5, 5,1, 7};
    const int mbb[NMERGED] = {6,4,2,0,5,3,1, 7,5,3,1, 5,1,3, 7,3, 3};

    const int warp = t >> 5, lane = t & 31;
    const int col = blockIdx.x * 8 + warp;
    for (int i = lane; i < 256; i += 32)
        amp[warp][i] = make_float2(i == col ? 1.f : 0.f, 0.f);
    __syncwarp();

    for (int gg = 0; gg < NMERGED; gg++) {
        int ba = mba[gg], bb = mbb[gg];
        int bl = min(ba, bb), bh = max(ba, bb);
        const int src = appOrder[gg];
        float2 m[16];
        #pragma unroll
        for (int i = 0; i < 16; i++) m[i] = mged[src][i];
        #pragma unroll
        for (int r = 0; r < 2; r++) {
            int p = lane + 32 * r;
            int q = ((p >> bl) << (bl + 1)) | (p & ((1 << bl) - 1));
            int base = ((q >> bh) << (bh + 1)) | (q & ((1 << bh) - 1));
            int i1 = base | (1 << bb);
            int i2 = base | (1 << ba);
            int i3 = i1 | i2;
            float2 vv[4] = { amp[warp][base], amp[warp][i1],
                             amp[warp][i2],   amp[warp][i3] };
            float2 nv[4];
            #pragma unroll
            for (int a = 0; a < 4; a++) {
                float2 acc = make_float2(0.f, 0.f);
                #pragma unroll
                for (int h = 0; h < 4; h++)
                    acc = cfma(m[a*4+h], vv[h], acc);
                nv[a] = acc;
            }
            amp[warp][base] = nv[0]; amp[warp][i1] = nv[1];
            amp[warp][i2]   = nv[2]; amp[warp][i3] = nv[3];
        }
        __syncwarp();
    }

    for (int k = lane; k < 256; k += 32)
        g_U[col * 256 + k] = amp[warp][k];
}

// ---------------------------------------------------------------------------
// Kernel 2: A[i][j] += sum_{k in chunk} sgn(k)*Re(conj(U[k,i])U[k,j]).
// grid (8,8,4): 32x32 output tile, k-chunk of 64; 16x16 threads, 2x2 frags.
// FIX vs R4: each thread loads 2 rows x 2 k-halves (tile is 32 wide in k,
// block is only 16 wide in x).
// ---------------------------------------------------------------------------
__global__ void __launch_bounds__(256) build_A()
{
    __shared__ float2 sa[32][33], sb[32][33];
    int tx = threadIdx.x, ty = threadIdx.y;      // 16x16
    int j0 = blockIdx.x * 32, i0 = blockIdx.y * 32, k0 = blockIdx.z * 64;
    float a00 = 0.f, a01 = 0.f, a10 = 0.f, a11 = 0.f;
    for (int kc = k0; kc < k0 + 64; kc += 32) {
        #pragma unroll
        for (int dy = 0; dy < 32; dy += 16) {
            #pragma unroll
            for (int dx = 0; dx < 32; dx += 16) {
                int k = kc + tx + dx;
                float sg = (k & 128) ? -1.f : 1.f;   // wire 0 <-> bit 7
                float2 va = g_U[(i0 + ty + dy) * 256 + k];
                sa[ty + dy][tx + dx] = make_float2(va.x * sg, va.y * sg);
                sb[ty + dy][tx + dx] = g_U[(j0 + ty + dy) * 256 + k];
            }
        }
        __syncthreads();
        #pragma unroll
        for (int kk = 0; kk < 32; kk++) {
            float2 A0 = sa[ty*2][kk],   A1 = sa[ty*2+1][kk];
            float2 B0 = sb[tx*2][kk],   B1 = sb[tx*2+1][kk];
            a00 = fmaf(A0.x, B0.x, fmaf(A0.y, B0.y, a00));
            a01 = fmaf(A0.x, B1.x, fmaf(A0.y, B1.y, a01));
            a10 = fmaf(A1.x, B0.x, fmaf(A1.y, B0.y, a10));
            a11 = fmaf(A1.x, B1.x, fmaf(A1.y, B1.y, a11));
        }
        __syncthreads();
    }
    int ib = i0 + ty * 2, jb = j0 + tx * 2;
    atomicAdd(&g_A[ib * 256 + jb],           a00);
    atomicAdd(&g_A[ib * 256 + jb + 1],       a01);
    atomicAdd(&g_A[(ib + 1) * 256 + jb],     a10);
    atomicAdd(&g_A[(ib + 1) * 256 + jb + 1], a11);
}

// ---------------------------------------------------------------------------
// Kernels 3+4: transform A into the 3^8 coefficient tensor over {I,X,Z}.
// ---------------------------------------------------------------------------
__global__ void stage1()   // qubits 0-3 (high nibbles)
{
    int o = blockIdx.x * 256 + threadIdx.x;       // 81*256 = 20736 exact
    int t = o >> 8;
    int ilo = (o >> 4) & 15, jlo = o & 15;
    int d0 = t / 27, r = t % 27;
    int d1 = r / 9; r %= 9;
    int d2 = r / 3, d3 = r % 3;
    int dg[4] = { d0, d1, d2, d3 };
    float sum = 0.f;
    #pragma unroll
    for (int c = 0; c < 16; c++) {
        int ihi = 0, jhi = 0; float sg = 1.f;
        #pragma unroll
        for (int w = 0; w < 4; w++) {
            int b = (c >> w) & 1;
            int d = dg[w];
            int iw = b;
            int jw = (d == 1) ? (1 - b) : b;
            if (d == 2 && b) sg = -sg;
            ihi |= iw << (3 - w);
            jhi |= jw << (3 - w);
        }
        sum += sg * g_A[(ihi * 16 + ilo) * 256 + (jhi * 16 + jlo)];
    }
    g_T1[o] = sum;
}

__global__ void stage2()   // qubits 4-7 (low nibbles); writes padded C rows
{
    int o = blockIdx.x * 256 + threadIdx.x;
    if (o >= 6561) return;
    if (o < 243) g_C[o * 28 + 27] = 0.f;          // zero pad column
    int thi = o / 81, tlo = o % 81;
    int d0 = tlo / 27, r = tlo % 27;
    int d1 = r / 9; r %= 9;
    int d2 = r / 3, d3 = r % 3;
    int dg[4] = { d0, d1, d2, d3 };
    float sum = 0.f;
    #pragma unroll
    for (int c = 0; c < 16; c++) {
        int ilo = 0, jlo = 0; float sg = 1.f;
        #pragma unroll
        for (int w = 0; w < 4; w++) {
            int b = (c >> w) & 1;
            int d = dg[w];
            int iw = b;
            int jw = (d == 1) ? (1 - b) : b;
            if (d == 2 && b) sg = -sg;
            ilo |= iw << (3 - w);
            jlo |= jw << (3 - w);
        }
        sum += sg * g_T1[thi * 256 + ilo * 16 + jlo];
    }
    g_C[(o / 27) * 28 + (o % 27)] = sum * (1.f / 256.f);
}

// ---------------------------------------------------------------------------
// Kernel 5: fused gemm (f32x2) + tanh + quantum eval + logits.
// 1024 blocks x 128 threads; warp handles 2 rows; C is L1-resident (27 KB).
// ---------------------------------------------------------------------------
__device__ __forceinline__ float pick3(int d, float sn, float cs)
{
    return (d == 0) ? 1.f : ((d == 1) ? sn : cs);
}

__global__ void __launch_bounds__(128) gemm_eval(const float* __restrict__ x,
                                                 const float* __restrict__ fcw,
                                                 const float* __restrict__ fcb,
                                                 const float* __restrict__ outw,
                                                 const float* __restrict__ outb,
                                                 float* __restrict__ logits)
{
    int warp = threadIdx.x >> 5, lane = threadIdx.x & 31;
    int row0 = blockIdx.x * 8 + warp * 2;
    const ulonglong2* __restrict__ x0 =
        (const ulonglong2*)(x + (size_t)row0 * INPUT_DIM);
    const ulonglong2* __restrict__ x1 = x0 + (INPUT_DIM / 4);
    const ulonglong2* __restrict__ w4 = (const ulonglong2*)fcw;

    unsigned long long p0[8], p1[8];
    #pragma unroll
    for (int q = 0; q < 8; q++) { p0[q] = 0ull; p1[q] = 0ull; }

    #pragma unroll 2
    for (int kc = lane; kc < INPUT_DIM / 4; kc += 32) {
        ulonglong2 xa = x0[kc];
        ulonglong2 xb = x1[kc];
        #pragma unroll
        for (int q = 0; q < 8; q++) {
            ulonglong2 wv = w4[q * (INPUT_DIM / 4) + kc];
            p0[q] = ffma2(xa.x, wv.x, p0[q]);
            p0[q] = ffma2(xa.y, wv.y, p0[q]);
            p1[q] = ffma2(xb.x, wv.x, p1[q]);
            p1[q] = ffma2(xb.y, wv.y, p1[q]);
        }
    }
    float acc0[8], acc1[8];
    #pragma unroll
    for (int q = 0; q < 8; q++) {
        acc0[q] = __uint_as_float((unsigned)(p0[q] & 0xffffffffull))
                + __uint_as_float((unsigned)(p0[q] >> 32));
        acc1[q] = __uint_as_float((unsigned)(p1[q] & 0xffffffffull))
                + __uint_as_float((unsigned)(p1[q] >> 32));
    }
    #pragma unroll
    for (int q = 0; q < 8; q++) {
        #pragma unroll
        for (int off = 16; off > 0; off >>= 1) {
            acc0[q] += __shfl_xor_sync(0xffffffffu, acc0[q], off);
            acc1[q] += __shfl_xor_sync(0xffffffffu, acc1[q], off);
        }
    }

    // ---- quantum eval: lanes 0-15 -> row0, lanes 16-31 -> row1 ----
    int half = lane >> 4;          // 0 or 1
    int part = lane & 15;
    float sn[8], cs[8];
    #pragma unroll
    for (int q = 0; q < 8; q++) {
        float f = tanhf((half ? acc1[q] : acc0[q]) + fcb[q]);
        __sincosf(f, &sn[q], &cs[q]);
    }

    float4 g4[7];
    {
        float* gp = (float*)g4;
        #pragma unroll
        for (int a = 0; a < 3; a++) {
            float ua = pick3(a, sn[5], cs[5]);
            #pragma unroll
            for (int b = 0; b < 3; b++) {
                float uab = ua * pick3(b, sn[6], cs[6]);
                #pragma unroll
                for (int c = 0; c < 3; c++)
                    gp[a * 9 + b * 3 + c] = uab * pick3(c, sn[7], cs[7]);
            }
        }
        gp[27] = 0.f;
    }

    float qacc = 0.f;
    for (int o = part; o < 243; o += 16) {
        int d0 = o / 81, r = o % 81;
        int d1 = r / 27; r %= 27;
        int d2 = r / 9;  r %= 9;
        int d3 = r / 3,  d4 = r % 3;
        float p = pick3(d0, sn[0], cs[0]) * pick3(d1, sn[1], cs[1]);
        p *= pick3(d2, sn[2], cs[2]);
        p *= pick3(d3, sn[3], cs[3]);
        p *= pick3(d4, sn[4], cs[4]);
        const float4* crow = (const float4*)(g_C + o * 28);
        float dsum = 0.f;
        #pragma unroll
        for (int j = 0; j < 7; j++) {
            float4 cv = crow[j], gv = g4[j];
            dsum = fmaf(cv.x, gv.x, dsum);
            dsum = fmaf(cv.y, gv.y, dsum);
            dsum = fmaf(cv.z, gv.z, dsum);
            dsum = fmaf(cv.w, gv.w, dsum);
        }
        qacc = fmaf(p, dsum, qacc);
    }
    // reduce within each 16-lane half
    qacc += __shfl_xor_sync(0xffffffffu, qacc, 1);
    qacc += __shfl_xor_sync(0xffffffffu, qacc, 2);
    qacc += __shfl_xor_sync(0xffffffffu, qacc, 4);
    qacc += __shfl_xor_sync(0xffffffffu, qacc, 8);

    if (part < NCLS)
        logits[(row0 + half) * NCLS + part] = fmaf(qacc, outw[part], outb[part]);
}

// ---------------------------------------------------------------------------
extern "C" void kernel_launch(void* const* d_in, const int* in_sizes, int n_in,
                              void* d_out, int out_size)
{
    const float* x    = (const float*)d_in[0];
    const float* fcw  = (const float*)d_in[1];
    const float* fcb  = (const float*)d_in[2];
    const float* conv = (const float*)d_in[3];
    const float* pool = (const float*)d_in[4];
    const float* last = (const float*)d_in[5];
    const float* outw = (const float*)d_in[6];
    const float* outb = (const float*)d_in[7];
    float* out = (float*)d_out;

    sim_all<<<32, 256>>>(conv, pool, last);
    build_A<<<dim3(8, 8, 4), dim3(16, 16)>>>();
    stage1<<<81, 256>>>();
    stage2<<<26, 256>>>();
    gemm_eval<<<1024, 128>>>(x, fcw, fcb, outw, outb, out);
}